// round 5
// baseline (speedup 1.0000x reference)
#include <cuda_runtime.h>

#define CIN 128
#define C 64
#define H2f 0.01f
#define NNODES 50000
#define NEDGES 800000
#define TE 128
#define GS 130
#define SMEM_EDGE ((64 * 128 + 64 * GS + TE * 3) * 4)

__device__ float g_deg[NNODES];
__device__ float g_W[NEDGES];
__device__ float g_buf[3][(long)NNODES * C];

// ---- packed f32x2 helpers ----
__device__ __forceinline__ void ffma2(unsigned long long& acc,
                                      unsigned long long a, unsigned long long b) {
    asm("fma.rn.f32x2 %0, %1, %2, %0;" : "+l"(acc) : "l"(a), "l"(b));
}
__device__ __forceinline__ float2 u2f2(unsigned long long u) {
    float2 f;
    asm("mov.b64 {%0, %1}, %2;" : "=f"(f.x), "=f"(f.y) : "l"(u));
    return f;
}
__device__ __forceinline__ unsigned long long f2u2(float x, float y) {
    unsigned long long u;
    asm("mov.b64 %0, {%1, %2};" : "=l"(u) : "f"(x), "f"(y));
    return u;
}
__device__ __forceinline__ float tanh_fast(float x) {
    float y;
    asm("tanh.approx.f32 %0, %1;" : "=f"(y) : "f"(x));
    return y;
}

// Fused: proj (blocks [0, nPB)) + zero g_deg (rest).
// proj writes x0 to buf0, buf1, buf2 (buf2 = layer-0 A since 2x0-x0 = x0).
__global__ void __launch_bounds__(256) k_pz(const float* __restrict__ xn,
                                            const float* __restrict__ K1,
                                            int nN, int nPB) {
    if (blockIdx.x >= nPB) {
        int i = (blockIdx.x - nPB) * 256 + threadIdx.x;
        if (i < nN) g_deg[i] = 0.0f;
        return;
    }
    __shared__ float Ks[C * CIN];
    __shared__ float xs[CIN * 64];
    int tid = threadIdx.x;
    for (int i = tid; i < C * CIN; i += 256) Ks[i] = K1[i];
    int n0 = blockIdx.x * 64;
    for (int i = tid; i < CIN * 64; i += 256) {
        int k = i >> 6, nl = i & 63;
        int n = n0 + nl;
        xs[i] = (n < nN) ? xn[(long)k * nN + n] : 0.0f;
    }
    __syncthreads();
    int nl = tid & 63;
    int cb = (tid >> 6) * 16;
    float acc[16];
#pragma unroll
    for (int j = 0; j < 16; j++) acc[j] = 0.0f;
    for (int k = 0; k < CIN; k++) {
        float xv = xs[k * 64 + nl];
#pragma unroll
        for (int j = 0; j < 16; j++) acc[j] = fmaf(Ks[(cb + j) * CIN + k], xv, acc[j]);
    }
    int n = n0 + nl;
    if (n < nN) {
#pragma unroll
        for (int j = 0; j < 16; j++) {
            float v = fmaxf(acc[j], 0.0f);
            g_buf[0][(long)n * C + cb + j] = v;
            g_buf[1][(long)n * C + cb + j] = v;
            g_buf[2][(long)n * C + cb + j] = v;
        }
    }
}

__global__ void k_degree(const int* __restrict__ Jv, int nE) {
    int e = blockIdx.x * blockDim.x + threadIdx.x;
    if (e < nE) atomicAdd(&g_deg[Jv[e]], 1.0f);
}

__global__ void k_Wd(const int* __restrict__ Iv, const int* __restrict__ Jv, int nE) {
    int e = blockIdx.x * blockDim.x + threadIdx.x;
    if (e < nE)
        g_W[e] = rsqrtf(g_deg[Iv[e]] + 1.0f) * rsqrtf(g_deg[Jv[e]] + 1.0f);
}

// A = 2*x_cur - x_old
__global__ void k_init(int curI, int oldI, int nxtI, int n4) {
    int i = blockIdx.x * blockDim.x + threadIdx.x;
    if (i >= n4) return;
    float4 a = ((const float4*)g_buf[curI])[i];
    float4 b = ((const float4*)g_buf[oldI])[i];
    ((float4*)g_buf[nxtI])[i] = make_float4(2.0f * a.x - b.x, 2.0f * a.y - b.y,
                                            2.0f * a.z - b.z, 2.0f * a.w - b.w);
}

// Warp-tile GEMM step: acc[r][p] (m = mbase+r, e-pair p) over 64 k.
// KtD rows are duplicated pairs: KtD[k*128 + 2m] = KtD[..+1] = Kmat(m, k).
__device__ __forceinline__ void gemm_tile(const float* __restrict__ KtD,
                                          const float* __restrict__ gcol,
                                          int koff,
                                          unsigned long long (&acc)[4][4]) {
#pragma unroll
    for (int r = 0; r < 4; r++)
#pragma unroll
        for (int p = 0; p < 4; p++) acc[r][p] = 0ull;
#pragma unroll 4
    for (int k = 0; k < 64; k++) {
        const float* kr = KtD + k * 128 + koff;
        ulonglong2 ka = *(const ulonglong2*)kr;        // dup K(m0), K(m0+1)
        ulonglong2 kb = *(const ulonglong2*)(kr + 4);  // dup K(m0+2), K(m0+3)
        const float* gr = gcol + k * GS;
        unsigned long long g0 = *(const unsigned long long*)(gr);
        unsigned long long g1 = *(const unsigned long long*)(gr + 2);
        unsigned long long g2 = *(const unsigned long long*)(gr + 4);
        unsigned long long g3 = *(const unsigned long long*)(gr + 6);
        ffma2(acc[0][0], ka.x, g0); ffma2(acc[0][1], ka.x, g1);
        ffma2(acc[0][2], ka.x, g2); ffma2(acc[0][3], ka.x, g3);
        ffma2(acc[1][0], ka.y, g0); ffma2(acc[1][1], ka.y, g1);
        ffma2(acc[1][2], ka.y, g2); ffma2(acc[1][3], ka.y, g3);
        ffma2(acc[2][0], kb.x, g0); ffma2(acc[2][1], kb.x, g1);
        ffma2(acc[2][2], kb.x, g2); ffma2(acc[2][3], kb.x, g3);
        ffma2(acc[3][0], kb.y, g0); ffma2(acc[3][1], kb.y, g1);
        ffma2(acc[3][2], kb.y, g2); ffma2(acc[3][3], kb.y, g3);
    }
}

// Hot kernel: block processes TE=128 edges/iter via two tiled 64x128 GEMMs.
// GT[64][GS]: g then t (row = k-dim, col = edge). Warp = 32(m) x 32(e) tile.
__global__ void __launch_bounds__(256, 2) k_edge(int xI, int aI,
        const int* __restrict__ Iv, const int* __restrict__ Jv,
        const float* __restrict__ Km, int nE)
{
    extern __shared__ float sm[];
    float* KtD = sm;                       // 64*128: KtD[a*128+2b(+1)] = K[b][a]
    float* GT  = sm + 64 * 128;            // 64*GS staging (g, then t)
    int*   sI  = (int*)(GT + 64 * GS);
    int*   sJ  = sI + TE;
    float* sW  = (float*)(sJ + TE);

    int tid = threadIdx.x;
    for (int i = tid; i < 4096; i += 256) {
        float v = Km[i];                   // K[o][c]
        int o = i >> 6, c = i & 63;
        KtD[c * 128 + 2 * o]     = v;      // GEMM1 view: row c, m=o -> K[o][c]
        KtD[c * 128 + 2 * o + 1] = v;      // (GEMM2 view row o, m=c -> K[c][o], same array)
    }

    const float2* x2 = (const float2*)g_buf[xI];
    float* A = g_buf[aI];
    int lane = tid & 31, wid = tid >> 5;
    int wo = wid >> 2, we = wid & 3;       // warp grid: 2(m) x 4(e)
    int to = lane >> 2, te = lane & 3;     // thread grid: 8(m) x 4(e)
    int koff  = wo * 64 + to * 8;          // 2*(m-base) into dup rows
    int mbase = wo * 32 + to * 4;
    int ebase = we * 32 + te * 8;
    const float* gcol = GT + ebase;
    unsigned long long acc[4][4];

    for (long e0 = (long)blockIdx.x * TE; e0 < nE; e0 += (long)gridDim.x * TE) {
        __syncthreads();                   // prior iter's smem reads complete
        if (tid < TE) {
            long e = e0 + tid;
            bool ok = e < (long)nE;
            sI[tid] = ok ? Iv[e] : 0;
            sJ[tid] = ok ? Jv[e] : 0;
            sW[tid] = ok ? g_W[e] : 0.0f;  // w=0 => edge contributes exactly 0
        }
        __syncthreads();
        // ---- gather: GT[c][e] = W*(x_I - x_J); warp handles 16 edges ----
        {
            float* r0 = GT + (2 * lane) * GS;
            float* r1 = r0 + GS;
            int eb = wid * 16;
#pragma unroll 4
            for (int el = 0; el < 16; el++) {
                int e = eb + el;
                int i = sI[e], j = sJ[e];
                float wgt = sW[e];
                float2 xi = x2[(long)i * 32 + lane];
                float2 xj = x2[(long)j * 32 + lane];
                r0[e] = wgt * (xi.x - xj.x);
                r1[e] = wgt * (xi.y - xj.y);
            }
        }
        __syncthreads();
        // ---- GEMM1: T = K * G ----
        gemm_tile(KtD, gcol, koff, acc);
        __syncthreads();
        // ---- tanh + store T into GT (row = o) ----
#pragma unroll
        for (int r = 0; r < 4; r++) {
            float* trow = GT + (mbase + r) * GS + ebase;
#pragma unroll
            for (int p = 0; p < 4; p++) {
                float2 f = u2f2(acc[r][p]);
                *(unsigned long long*)(trow + 2 * p) =
                    f2u2(tanh_fast(f.x), tanh_fast(f.y));
            }
        }
        __syncthreads();
        // ---- GEMM2: D = K^T-view * T ----
        gemm_tile(KtD, gcol, koff, acc);
        // ---- scatter: A[I] -= H^2*W*d ; A[J] += H^2*W*d (RED.v4 from regs) ----
#pragma unroll
        for (int j = 0; j < 8; j++) {
            const int p = j >> 1;
            int e = ebase + j;
            float s = H2f * sW[e];
            int ni = sI[e], nj = sJ[e];
            float2 f0 = u2f2(acc[0][p]);
            float2 f1 = u2f2(acc[1][p]);
            float2 f2 = u2f2(acc[2][p]);
            float2 f3 = u2f2(acc[3][p]);
            float v0 = (j & 1) ? f0.y : f0.x;
            float v1 = (j & 1) ? f1.y : f1.x;
            float v2 = (j & 1) ? f2.y : f2.x;
            float v3 = (j & 1) ? f3.y : f3.x;
            float* pi = A + (long)ni * 64 + mbase;
            float* pj = A + (long)nj * 64 + mbase;
            asm volatile("red.global.add.v4.f32 [%0], {%1, %2, %3, %4};"
                         :: "l"(pi), "f"(-s * v0), "f"(-s * v1),
                            "f"(-s * v2), "f"(-s * v3) : "memory");
            asm volatile("red.global.add.v4.f32 [%0], {%1, %2, %3, %4};"
                         :: "l"(pj), "f"(s * v0), "f"(s * v1),
                            "f"(s * v2), "f"(s * v3) : "memory");
        }
    }
}

// out[n][o] = sum_c KNclose[o][c] * x[n][c]
__global__ void __launch_bounds__(128) k_out(int xIdx, const float* __restrict__ KNc,
                                             float* __restrict__ out, int nN, int nOut) {
    __shared__ float Ks[40 * C];
    for (int i = threadIdx.x; i < nOut * C; i += 128) Ks[i] = KNc[i];
    __syncthreads();
    int n = blockIdx.x * 128 + threadIdx.x;
    if (n >= nN) return;
    const float* xr = g_buf[xIdx] + (long)n * C;
    float xv[C];
#pragma unroll
    for (int q = 0; q < C / 4; q++) {
        float4 v = ((const float4*)xr)[q];
        xv[4 * q] = v.x; xv[4 * q + 1] = v.y; xv[4 * q + 2] = v.z; xv[4 * q + 3] = v.w;
    }
    for (int o = 0; o < nOut; o++) {
        float acc = 0.0f;
#pragma unroll
        for (int c = 0; c < C; c++) acc = fmaf(Ks[o * C + c], xv[c], acc);
        out[(long)n * nOut + o] = acc;
    }
}

extern "C" void kernel_launch(void* const* d_in, const int* in_sizes, int n_in,
                              void* d_out, int out_size) {
    const float* xn = (const float*)d_in[0];
    const int* Iv = (const int*)d_in[1];
    const int* Jv = (const int*)d_in[2];
    int idx = 3;
    if (n_in >= 7 && in_sizes[3] == 1) idx = 4;   // skip scalar n_nodes input
    const float* K1  = (const float*)d_in[idx];
    const float* KN2 = (const float*)d_in[idx + 1];
    const float* KNc = (const float*)d_in[idx + 2];
    int nE = in_sizes[1];
    int nN = in_sizes[0] / CIN;
    int nLayer = in_sizes[idx + 1] / (C * C);
    int nOut = in_sizes[idx + 2] / C;
    float* out = (float*)d_out;

    cudaFuncSetAttribute(k_edge, cudaFuncAttributeMaxDynamicSharedMemorySize,
                         SMEM_EDGE);

    int nPB = (nN + 63) / 64;
    int nZB = (nN + 255) / 256;
    k_pz<<<nPB + nZB, 256>>>(xn, K1, nN, nPB);            // launch 0
    k_degree<<<(nE + 255) / 256, 256>>>(Jv, nE);          // launch 1
    k_Wd<<<(nE + 255) / 256, 256>>>(Iv, Jv, nE);          // launch 2

    int cur = 0, old = 1, nxt = 2;
    int n4 = nN * C / 4;
    for (int l = 0; l < nLayer; l++) {
        if (l > 0)
            k_init<<<(n4 + 255) / 256, 256>>>(cur, old, nxt, n4);
        k_edge<<<304, 256, SMEM_EDGE>>>(cur, nxt, Iv, Jv,
                                        KN2 + (long)l * C * C, nE);
        int t = old; old = cur; cur = nxt; nxt = t;
    }
    k_out<<<(nN + 127) / 128, 128>>>(cur, KNc, out, nN, nOut);
}

// round 7
// speedup vs baseline: 2.0303x; 2.0303x over previous
#include <cuda_runtime.h>
#include <cuda_bf16.h>
#include <cstdint>

#define CIN 128
#define C 64
#define H2f 0.01f
#define NNODES 50000
#define NEDGES 800000
#define TE 128
#define GSB 72          // smem tile row stride in bf16 (144B: 4-bank rotation/row)

__device__ float g_deg[NNODES];
__device__ float g_W[NEDGES];
__device__ float g_buf[3][(long)NNODES * C];

// ---------------- helpers ----------------
__device__ __forceinline__ uint32_t smem_u32(const void* p) {
    uint32_t a;
    asm("{ .reg .u64 t; cvta.to.shared.u64 t, %1; cvt.u32.u64 %0, t; }"
        : "=r"(a) : "l"(p));
    return a;
}
__device__ __forceinline__ float tanh_fast(float x) {
    float y;
    asm("tanh.approx.f32 %0, %1;" : "=f"(y) : "f"(x));
    return y;
}
// pack bf16x2: lo = a, hi = b
__device__ __forceinline__ uint32_t bf16x2_pack(float a, float b) {
    uint32_t r;
    asm("cvt.rn.satfinite.bf16x2.f32 %0, %1, %2;" : "=r"(r) : "f"(b), "f"(a));
    return r;
}
__device__ __forceinline__ void ldsm4(uint32_t (&r)[4], uint32_t addr) {
    asm volatile("ldmatrix.sync.aligned.m8n8.x4.shared.b16 {%0,%1,%2,%3}, [%4];"
        : "=r"(r[0]), "=r"(r[1]), "=r"(r[2]), "=r"(r[3]) : "r"(addr));
}
__device__ __forceinline__ void mma_bf16(float (&d)[4], const uint32_t (&a)[4],
                                         const uint32_t* b) {
    asm volatile("mma.sync.aligned.m16n8k16.row.col.f32.bf16.bf16.f32 "
        "{%0,%1,%2,%3}, {%4,%5,%6,%7}, {%8,%9}, {%0,%1,%2,%3};"
        : "+f"(d[0]), "+f"(d[1]), "+f"(d[2]), "+f"(d[3])
        : "r"(a[0]), "r"(a[1]), "r"(a[2]), "r"(a[3]), "r"(b[0]), "r"(b[1]));
}

// ---------------- setup kernels ----------------
// Fused: proj (blocks [0, nPB)) + zero g_deg (rest).
// proj writes x0 to buf0, buf1, buf2 (buf2 = layer-0 A since 2x0-x0 = x0).
__global__ void __launch_bounds__(256) k_pz(const float* __restrict__ xn,
                                            const float* __restrict__ K1,
                                            int nN, int nPB) {
    if (blockIdx.x >= nPB) {
        int i = (blockIdx.x - nPB) * 256 + threadIdx.x;
        if (i < nN) g_deg[i] = 0.0f;
        return;
    }
    __shared__ float Ks[C * CIN];
    __shared__ float xs[CIN * 64];
    int tid = threadIdx.x;
    for (int i = tid; i < C * CIN; i += 256) Ks[i] = K1[i];
    int n0 = blockIdx.x * 64;
    for (int i = tid; i < CIN * 64; i += 256) {
        int k = i >> 6, nl = i & 63;
        int n = n0 + nl;
        xs[i] = (n < nN) ? xn[(long)k * nN + n] : 0.0f;
    }
    __syncthreads();
    int nl = tid & 63;
    int cb = (tid >> 6) * 16;
    float acc[16];
#pragma unroll
    for (int j = 0; j < 16; j++) acc[j] = 0.0f;
    for (int k = 0; k < CIN; k++) {
        float xv = xs[k * 64 + nl];
#pragma unroll
        for (int j = 0; j < 16; j++) acc[j] = fmaf(Ks[(cb + j) * CIN + k], xv, acc[j]);
    }
    int n = n0 + nl;
    if (n < nN) {
#pragma unroll
        for (int j = 0; j < 16; j++) {
            float v = fmaxf(acc[j], 0.0f);
            g_buf[0][(long)n * C + cb + j] = v;
            g_buf[1][(long)n * C + cb + j] = v;
            g_buf[2][(long)n * C + cb + j] = v;
        }
    }
}

__global__ void k_degree(const int* __restrict__ Jv, int nE) {
    int e = blockIdx.x * blockDim.x + threadIdx.x;
    if (e < nE) atomicAdd(&g_deg[Jv[e]], 1.0f);
}

__global__ void k_Wd(const int* __restrict__ Iv, const int* __restrict__ Jv, int nE) {
    int e = blockIdx.x * blockDim.x + threadIdx.x;
    if (e < nE)
        g_W[e] = rsqrtf(g_deg[Iv[e]] + 1.0f) * rsqrtf(g_deg[Jv[e]] + 1.0f);
}

// A = 2*x_cur - x_old
__global__ void k_init(int curI, int oldI, int nxtI, int n4) {
    int i = blockIdx.x * blockDim.x + threadIdx.x;
    if (i >= n4) return;
    float4 a = ((const float4*)g_buf[curI])[i];
    float4 b = ((const float4*)g_buf[oldI])[i];
    ((float4*)g_buf[nxtI])[i] = make_float4(2.0f * a.x - b.x, 2.0f * a.y - b.y,
                                            2.0f * a.z - b.z, 2.0f * a.w - b.w);
}

// ---------------- hot kernel: mma.sync bf16 ----------------
// Per block-iter: 128 edges, two GEMMs D[128e x 64n] = A[128e x 64k] * B,
// B[k][n] = Km[n*64+k] identical for both GEMMs (held in registers per warp).
// Warp grid: 4 (edge tiles of 32) x 2 (n halves of 32). mma.sync m16n8k16.
__global__ void __launch_bounds__(256, 2)
k_edge(int xI, int aI, const int* __restrict__ Iv, const int* __restrict__ Jv,
       const float* __restrict__ Km, int nE)
{
    __shared__ __align__(16) __nv_bfloat16 Gt[TE * GSB];   // 18KB g tile
    __shared__ __align__(16) __nv_bfloat16 Tt[TE * GSB];   // 18KB t tile
    __shared__ int sI[TE], sJ[TE];
    __shared__ float sW[TE];

    int tid = threadIdx.x, lane = tid & 31, wid = tid >> 5;
    int gid = lane >> 2, tig = lane & 3;
    int wm = wid & 3, wn = wid >> 2;
    int mbase = wm * 32, nbase = wn * 32;

    // ---- persistent B fragments: b[kt][nt] over k=kt*16.., n=nbase+nt*8.. ----
    uint32_t bf[4][4][2];
    {
        int n = nbase + gid;          // + nt*8 below
#pragma unroll
        for (int nt = 0; nt < 4; nt++) {
            const float* kr = Km + (long)(n + nt * 8) * 64;
#pragma unroll
            for (int kt = 0; kt < 4; kt++) {
                int k0 = kt * 16 + tig * 2;
                bf[kt][nt][0] = bf16x2_pack(kr[k0], kr[k0 + 1]);
                bf[kt][nt][1] = bf16x2_pack(kr[k0 + 8], kr[k0 + 9]);
            }
        }
    }

    uint32_t gb = smem_u32(Gt), tb = smem_u32(Tt);
    // ldmatrix lane address offsets (row/col within 16x16 tile)
    int lrow = (lane & 7) + ((lane >> 3) & 1) * 8;
    int lcol = ((lane >> 4) & 1) * 8;

    const float2* x2 = (const float2*)g_buf[xI];
    float* A = g_buf[aI];

    for (long e0 = (long)blockIdx.x * TE; e0 < nE; e0 += (long)gridDim.x * TE) {
        __syncthreads();
        if (tid < TE) {
            long e = e0 + tid;
            bool ok = e < (long)nE;
            sI[tid] = ok ? Iv[e] : 0;
            sJ[tid] = ok ? Jv[e] : 0;
            sW[tid] = ok ? g_W[e] : 0.0f;   // w=0 => zero contribution
        }
        __syncthreads();
        // ---- gather: Gt[e][c] = bf16(W*(x_I - x_J)); warp: 16 edges ----
        {
            int eb = wid * 16;
#pragma unroll 4
            for (int el = 0; el < 16; el++) {
                int e = eb + el;
                float w = sW[e];
                float2 xi = x2[(long)sI[e] * 32 + lane];
                float2 xj = x2[(long)sJ[e] * 32 + lane];
                *(uint32_t*)((char*)Gt + e * (GSB * 2) + lane * 4) =
                    bf16x2_pack(w * (xi.x - xj.x), w * (xi.y - xj.y));
            }
        }
        __syncthreads();
        // ---- GEMM1: T = G * B ----
        float acc[2][4][4];
#pragma unroll
        for (int mt = 0; mt < 2; mt++)
#pragma unroll
            for (int nt = 0; nt < 4; nt++)
#pragma unroll
                for (int q = 0; q < 4; q++) acc[mt][nt][q] = 0.0f;
#pragma unroll
        for (int kt = 0; kt < 4; kt++) {
#pragma unroll
            for (int mt = 0; mt < 2; mt++) {
                uint32_t af[4];
                int row = mbase + mt * 16 + lrow;
                int col = kt * 16 + lcol;
                ldsm4(af, gb + row * (GSB * 2) + col * 2);
#pragma unroll
                for (int nt = 0; nt < 4; nt++)
                    mma_bf16(acc[mt][nt], af, bf[kt][nt]);
            }
        }
        // ---- tanh -> Tt (bf16) ----
#pragma unroll
        for (int mt = 0; mt < 2; mt++) {
            int er = mbase + mt * 16 + gid;
#pragma unroll
            for (int nt = 0; nt < 4; nt++) {
                int o = nbase + nt * 8 + tig * 2;
                *(uint32_t*)((char*)Tt + er * (GSB * 2) + o * 2) =
                    bf16x2_pack(tanh_fast(acc[mt][nt][0]), tanh_fast(acc[mt][nt][1]));
                *(uint32_t*)((char*)Tt + (er + 8) * (GSB * 2) + o * 2) =
                    bf16x2_pack(tanh_fast(acc[mt][nt][2]), tanh_fast(acc[mt][nt][3]));
            }
        }
        __syncthreads();
        // ---- GEMM2: D = T * B ----
#pragma unroll
        for (int mt = 0; mt < 2; mt++)
#pragma unroll
            for (int nt = 0; nt < 4; nt++)
#pragma unroll
                for (int q = 0; q < 4; q++) acc[mt][nt][q] = 0.0f;
#pragma unroll
        for (int kt = 0; kt < 4; kt++) {
#pragma unroll
            for (int mt = 0; mt < 2; mt++) {
                uint32_t af[4];
                int row = mbase + mt * 16 + lrow;
                int col = kt * 16 + lcol;
                ldsm4(af, tb + row * (GSB * 2) + col * 2);
#pragma unroll
                for (int nt = 0; nt < 4; nt++)
                    mma_bf16(acc[mt][nt], af, bf[kt][nt]);
            }
        }
        // ---- scatter: A[I] -= H^2*W*d ; A[J] += H^2*W*d (RED.v2) ----
#pragma unroll
        for (int mt = 0; mt < 2; mt++) {
#pragma unroll
            for (int half = 0; half < 2; half++) {
                int er = mbase + mt * 16 + gid + half * 8;
                float s = H2f * sW[er];
                long ni = sI[er], nj = sJ[er];
                float* pi = A + ni * 64;
                float* pj = A + nj * 64;
#pragma unroll
                for (int nt = 0; nt < 4; nt++) {
                    int c = nbase + nt * 8 + tig * 2;
                    float v0 = s * acc[mt][nt][2 * half];
                    float v1 = s * acc[mt][nt][2 * half + 1];
                    asm volatile("red.global.add.v2.f32 [%0], {%1, %2};"
                                 :: "l"(pi + c), "f"(-v0), "f"(-v1) : "memory");
                    asm volatile("red.global.add.v2.f32 [%0], {%1, %2};"
                                 :: "l"(pj + c), "f"(v0), "f"(v1) : "memory");
                }
            }
        }
    }
}

// out[n][o] = sum_c KNclose[o][c] * x[n][c]
__global__ void __launch_bounds__(128) k_out(int xIdx, const float* __restrict__ KNc,
                                             float* __restrict__ out, int nN, int nOut) {
    __shared__ float Ks[40 * C];
    for (int i = threadIdx.x; i < nOut * C; i += 128) Ks[i] = KNc[i];
    __syncthreads();
    int n = blockIdx.x * 128 + threadIdx.x;
    if (n >= nN) return;
    const float* xr = g_buf[xIdx] + (long)n * C;
    float xv[C];
#pragma unroll
    for (int q = 0; q < C / 4; q++) {
        float4 v = ((const float4*)xr)[q];
        xv[4 * q] = v.x; xv[4 * q + 1] = v.y; xv[4 * q + 2] = v.z; xv[4 * q + 3] = v.w;
    }
    for (int o = 0; o < nOut; o++) {
        float acc = 0.0f;
#pragma unroll
        for (int c = 0; c < C; c++) acc = fmaf(Ks[o * C + c], xv[c], acc);
        out[(long)n * nOut + o] = acc;
    }
}

extern "C" void kernel_launch(void* const* d_in, const int* in_sizes, int n_in,
                              void* d_out, int out_size) {
    const float* xn = (const float*)d_in[0];
    const int* Iv = (const int*)d_in[1];
    const int* Jv = (const int*)d_in[2];
    int idx = 3;
    if (n_in >= 7 && in_sizes[3] == 1) idx = 4;   // skip scalar n_nodes input
    const float* K1  = (const float*)d_in[idx];
    const float* KN2 = (const float*)d_in[idx + 1];
    const float* KNc = (const float*)d_in[idx + 2];
    int nE = in_sizes[1];
    int nN = in_sizes[0] / CIN;
    int nLayer = in_sizes[idx + 1] / (C * C);
    int nOut = in_sizes[idx + 2] / C;
    float* out = (float*)d_out;

    int nPB = (nN + 63) / 64;
    int nZB = (nN + 255) / 256;
    k_pz<<<nPB + nZB, 256>>>(xn, K1, nN, nPB);            // launch 0
    k_degree<<<(nE + 255) / 256, 256>>>(Jv, nE);          // launch 1
    k_Wd<<<(nE + 255) / 256, 256>>>(Iv, Jv, nE);          // launch 2

    int cur = 0, old = 1, nxt = 2;
    int n4 = nN * C / 4;
    for (int l = 0; l < nLayer; l++) {
        if (l > 0)
            k_init<<<(n4 + 255) / 256, 256>>>(cur, old, nxt, n4);
        k_edge<<<304, 256>>>(cur, nxt, Iv, Jv, KN2 + (long)l * C * C, nE);
        int t = old; old = cur; cur = nxt; nxt = t;
    }
    k_out<<<(nN + 127) / 128, 128>>>(cur, KNc, out, nN, nOut);
}

// round 8
// speedup vs baseline: 2.5762x; 1.2689x over previous
#include <cuda_runtime.h>
#include <cuda_bf16.h>
#include <cstdint>

#define CIN 128
#define C 64
#define H2f 0.01f
#define NNODES 50000
#define NEDGES 800000
#define TE 128
#define GSB 72          // smem tile row stride in bf16 (144B)

#define GT_BYTES (TE * GSB * 2)
#define SMEM_EDGE (2 * GT_BYTES + GT_BYTES + 4 * TE * 12)

__device__ float g_deg[NNODES];
__device__ float g_W[NEDGES];
__device__ float g_buf[3][(long)NNODES * C];

// ---------------- helpers ----------------
__device__ __forceinline__ uint32_t smem_u32(const void* p) {
    uint32_t a;
    asm("{ .reg .u64 t; cvta.to.shared.u64 t, %1; cvt.u32.u64 %0, t; }"
        : "=r"(a) : "l"(p));
    return a;
}
__device__ __forceinline__ float tanh_fast(float x) {
    float y;
    asm("tanh.approx.f32 %0, %1;" : "=f"(y) : "f"(x));
    return y;
}
// pack bf16x2: lo = a, hi = b
__device__ __forceinline__ uint32_t bf16x2_pack(float a, float b) {
    uint32_t r;
    asm("cvt.rn.satfinite.bf16x2.f32 %0, %1, %2;" : "=r"(r) : "f"(b), "f"(a));
    return r;
}
__device__ __forceinline__ void ldsm4(uint32_t (&r)[4], uint32_t addr) {
    asm volatile("ldmatrix.sync.aligned.m8n8.x4.shared.b16 {%0,%1,%2,%3}, [%4];"
        : "=r"(r[0]), "=r"(r[1]), "=r"(r[2]), "=r"(r[3]) : "r"(addr));
}
__device__ __forceinline__ void mma_bf16(float (&d)[4], const uint32_t (&a)[4],
                                         const uint32_t* b) {
    asm volatile("mma.sync.aligned.m16n8k16.row.col.f32.bf16.bf16.f32 "
        "{%0,%1,%2,%3}, {%4,%5,%6,%7}, {%8,%9}, {%0,%1,%2,%3};"
        : "+f"(d[0]), "+f"(d[1]), "+f"(d[2]), "+f"(d[3])
        : "r"(a[0]), "r"(a[1]), "r"(a[2]), "r"(a[3]), "r"(b[0]), "r"(b[1]));
}

// ---------------- setup kernels ----------------
__global__ void __launch_bounds__(256) k_pz(const float* __restrict__ xn,
                                            const float* __restrict__ K1,
                                            int nN, int nPB) {
    if (blockIdx.x >= nPB) {
        int i = (blockIdx.x - nPB) * 256 + threadIdx.x;
        if (i < nN) g_deg[i] = 0.0f;
        return;
    }
    __shared__ float Ks[C * CIN];
    __shared__ float xs[CIN * 64];
    int tid = threadIdx.x;
    for (int i = tid; i < C * CIN; i += 256) Ks[i] = K1[i];
    int n0 = blockIdx.x * 64;
    for (int i = tid; i < CIN * 64; i += 256) {
        int k = i >> 6, nl = i & 63;
        int n = n0 + nl;
        xs[i] = (n < nN) ? xn[(long)k * nN + n] : 0.0f;
    }
    __syncthreads();
    int nl = tid & 63;
    int cb = (tid >> 6) * 16;
    float acc[16];
#pragma unroll
    for (int j = 0; j < 16; j++) acc[j] = 0.0f;
    for (int k = 0; k < CIN; k++) {
        float xv = xs[k * 64 + nl];
#pragma unroll
        for (int j = 0; j < 16; j++) acc[j] = fmaf(Ks[(cb + j) * CIN + k], xv, acc[j]);
    }
    int n = n0 + nl;
    if (n < nN) {
#pragma unroll
        for (int j = 0; j < 16; j++) {
            float v = fmaxf(acc[j], 0.0f);
            g_buf[0][(long)n * C + cb + j] = v;
            g_buf[1][(long)n * C + cb + j] = v;
            g_buf[2][(long)n * C + cb + j] = v;
        }
    }
}

__global__ void k_degree(const int* __restrict__ Jv, int nE) {
    int e = blockIdx.x * blockDim.x + threadIdx.x;
    if (e < nE) atomicAdd(&g_deg[Jv[e]], 1.0f);
}

__global__ void k_Wd(const int* __restrict__ Iv, const int* __restrict__ Jv, int nE) {
    int e = blockIdx.x * blockDim.x + threadIdx.x;
    if (e < nE)
        g_W[e] = rsqrtf(g_deg[Iv[e]] + 1.0f) * rsqrtf(g_deg[Jv[e]] + 1.0f);
}

__global__ void k_init(int curI, int oldI, int nxtI, int n4) {
    int i = blockIdx.x * blockDim.x + threadIdx.x;
    if (i >= n4) return;
    float4 a = ((const float4*)g_buf[curI])[i];
    float4 b = ((const float4*)g_buf[oldI])[i];
    ((float4*)g_buf[nxtI])[i] = make_float4(2.0f * a.x - b.x, 2.0f * a.y - b.y,
                                            2.0f * a.z - b.z, 2.0f * a.w - b.w);
}

// ---------------- hot kernel: mma.sync bf16, software-pipelined ----------------
// Pipeline (per local iter n, tile k): PhaseA = idx-prefetch(k+2) + GEMM1(k)
// interleaved with x-gather(k+1) + tanh->Tt ; sync ; PhaseB = GEMM2(k)+scatter(k).
// Gt double-buffered; idx in 4-slot ring (prefetch k+2, gather k+1, scatter k).
__global__ void __launch_bounds__(256, 2)
k_edge(int xI, int aI, const int* __restrict__ Iv, const int* __restrict__ Jv,
       const float* __restrict__ Km, int nE)
{
    extern __shared__ __align__(16) char smem[];
    __nv_bfloat16* GtA = (__nv_bfloat16*)smem;
    __nv_bfloat16* GtB = (__nv_bfloat16*)(smem + GT_BYTES);
    __nv_bfloat16* Tt  = (__nv_bfloat16*)(smem + 2 * GT_BYTES);
    int*   sI = (int*)(smem + 3 * GT_BYTES);          // [4][TE]
    int*   sJ = sI + 4 * TE;
    float* sW = (float*)(sJ + 4 * TE);

    int tid = threadIdx.x, lane = tid & 31, wid = tid >> 5;
    int gid = lane >> 2, tig = lane & 3;
    int wm = wid & 3, wn = wid >> 2;
    int mbase = wm * 32, nbase = wn * 32;

    // ---- persistent B fragments ----
    uint32_t bfr[4][4][2];
    {
        int n = nbase + gid;
#pragma unroll
        for (int nt = 0; nt < 4; nt++) {
            const float* kr = Km + (long)(n + nt * 8) * 64;
#pragma unroll
            for (int kt = 0; kt < 4; kt++) {
                int k0 = kt * 16 + tig * 2;
                bfr[kt][nt][0] = bf16x2_pack(kr[k0], kr[k0 + 1]);
                bfr[kt][nt][1] = bf16x2_pack(kr[k0 + 8], kr[k0 + 9]);
            }
        }
    }

    uint32_t gba = smem_u32(GtA), gbb = smem_u32(GtB), tb = smem_u32(Tt);
    int lrow = (lane & 7) + ((lane >> 3) & 1) * 8;
    int lcol = ((lane >> 4) & 1) * 8;

    const float2* x2 = (const float2*)g_buf[xI];
    float* A = g_buf[aI];
    long stride = (long)gridDim.x * TE;
    long e0 = (long)blockIdx.x * TE;

    // idx loader: slot s <- tile at base eb
    auto load_idx = [&](long eb, int s) {
        if (tid < TE) {
            long e = eb + tid;
            bool ok = e < (long)nE;
            sI[s * TE + tid] = ok ? Iv[e] : 0;
            sJ[s * TE + tid] = ok ? Jv[e] : 0;
            sW[s * TE + tid] = ok ? g_W[e] : 0.0f;
        }
    };

    // ---- prologue: idx slots 0,1; gather tile 0 into GtA ----
    load_idx(e0, 0);
    load_idx(e0 + stride, 1);
    __syncthreads();
    {
        int eb = wid * 16;
#pragma unroll 4
        for (int el = 0; el < 16; el++) {
            int e = eb + el;
            float w = sW[e];
            float2 xi = x2[(long)sI[e] * 32 + lane];
            float2 xj = x2[(long)sJ[e] * 32 + lane];
            *(uint32_t*)((char*)GtA + e * (GSB * 2) + lane * 4) =
                bf16x2_pack(w * (xi.x - xj.x), w * (xi.y - xj.y));
        }
    }

    int s0 = 0;                         // idx slot of current tile
    int curbuf = 0;                     // Gt buffer of current tile
    for (; e0 < nE; e0 += stride) {
        int s1 = (s0 + 1) & 3, s2 = (s0 + 2) & 3;
        uint32_t gcur = curbuf ? gbb : gba;
        char* gnext = (char*)(curbuf ? GtA : GtB);
        __syncthreads();                // Gt[cur], Tt consumed, idx slots ready
        // ---- Phase A ----
        load_idx(e0 + 2 * stride, s2);  // idx prefetch (tile k+2)

        float acc[2][4][4];
#pragma unroll
        for (int mt = 0; mt < 2; mt++)
#pragma unroll
            for (int nt = 0; nt < 4; nt++)
#pragma unroll
                for (int q = 0; q < 4; q++) acc[mt][nt][q] = 0.0f;

        const int* sIc = sI + s1 * TE;
        const int* sJc = sJ + s1 * TE;
        const float* sWc = sW + s1 * TE;
        int ebg = wid * 16;
        float2 xi[8], xj[8];
        // wave 0 loads (edges 0-7 of this warp's 16, tile k+1)
#pragma unroll
        for (int el = 0; el < 8; el++) {
            int e = ebg + el;
            xi[el] = x2[(long)sIc[e] * 32 + lane];
            xj[el] = x2[(long)sJc[e] * 32 + lane];
        }
        // GEMM1 kt = 0,1  (covers wave-0 latency)
#pragma unroll
        for (int kt = 0; kt < 2; kt++)
#pragma unroll
            for (int mt = 0; mt < 2; mt++) {
                uint32_t af[4];
                ldsm4(af, gcur + (mbase + mt * 16 + lrow) * (GSB * 2)
                              + (kt * 16 + lcol) * 2);
#pragma unroll
                for (int nt = 0; nt < 4; nt++) mma_bf16(acc[mt][nt], af, bfr[kt][nt]);
            }
        // store wave 0
#pragma unroll
        for (int el = 0; el < 8; el++) {
            int e = ebg + el;
            float w = sWc[e];
            *(uint32_t*)(gnext + e * (GSB * 2) + lane * 4) =
                bf16x2_pack(w * (xi[el].x - xj[el].x), w * (xi[el].y - xj[el].y));
        }
        // wave 1 loads (edges 8-15)
#pragma unroll
        for (int el = 0; el < 8; el++) {
            int e = ebg + 8 + el;
            xi[el] = x2[(long)sIc[e] * 32 + lane];
            xj[el] = x2[(long)sJc[e] * 32 + lane];
        }
        // GEMM1 kt = 2,3
#pragma unroll
        for (int kt = 2; kt < 4; kt++)
#pragma unroll
            for (int mt = 0; mt < 2; mt++) {
                uint32_t af[4];
                ldsm4(af, gcur + (mbase + mt * 16 + lrow) * (GSB * 2)
                              + (kt * 16 + lcol) * 2);
#pragma unroll
                for (int nt = 0; nt < 4; nt++) mma_bf16(acc[mt][nt], af, bfr[kt][nt]);
            }
        // store wave 1
#pragma unroll
        for (int el = 0; el < 8; el++) {
            int e = ebg + 8 + el;
            float w = sWc[e];
            *(uint32_t*)(gnext + e * (GSB * 2) + lane * 4) =
                bf16x2_pack(w * (xi[el].x - xj[el].x), w * (xi[el].y - xj[el].y));
        }
        // tanh -> Tt
#pragma unroll
        for (int mt = 0; mt < 2; mt++) {
            int er = mbase + mt * 16 + gid;
#pragma unroll
            for (int nt = 0; nt < 4; nt++) {
                int o = nbase + nt * 8 + tig * 2;
                *(uint32_t*)((char*)Tt + er * (GSB * 2) + o * 2) =
                    bf16x2_pack(tanh_fast(acc[mt][nt][0]), tanh_fast(acc[mt][nt][1]));
                *(uint32_t*)((char*)Tt + (er + 8) * (GSB * 2) + o * 2) =
                    bf16x2_pack(tanh_fast(acc[mt][nt][2]), tanh_fast(acc[mt][nt][3]));
            }
        }
        __syncthreads();
        // ---- Phase B: GEMM2 + scatter (tile k, idx slot s0) ----
#pragma unroll
        for (int mt = 0; mt < 2; mt++)
#pragma unroll
            for (int nt = 0; nt < 4; nt++)
#pragma unroll
                for (int q = 0; q < 4; q++) acc[mt][nt][q] = 0.0f;
#pragma unroll
        for (int kt = 0; kt < 4; kt++)
#pragma unroll
            for (int mt = 0; mt < 2; mt++) {
                uint32_t af[4];
                ldsm4(af, tb + (mbase + mt * 16 + lrow) * (GSB * 2)
                             + (kt * 16 + lcol) * 2);
#pragma unroll
                for (int nt = 0; nt < 4; nt++) mma_bf16(acc[mt][nt], af, bfr[kt][nt]);
            }
        const int* sIs = sI + s0 * TE;
        const int* sJs = sJ + s0 * TE;
        const float* sWs = sW + s0 * TE;
#pragma unroll
        for (int mt = 0; mt < 2; mt++) {
#pragma unroll
            for (int half = 0; half < 2; half++) {
                int er = mbase + mt * 16 + gid + half * 8;
                float s = H2f * sWs[er];
                long ni = sIs[er], nj = sJs[er];
                float* pi = A + ni * 64;
                float* pj = A + nj * 64;
#pragma unroll
                for (int nt = 0; nt < 4; nt++) {
                    int c = nbase + nt * 8 + tig * 2;
                    float v0 = s * acc[mt][nt][2 * half];
                    float v1 = s * acc[mt][nt][2 * half + 1];
                    asm volatile("red.global.add.v2.f32 [%0], {%1, %2};"
                                 :: "l"(pi + c), "f"(-v0), "f"(-v1) : "memory");
                    asm volatile("red.global.add.v2.f32 [%0], {%1, %2};"
                                 :: "l"(pj + c), "f"(v0), "f"(v1) : "memory");
                }
            }
        }
        s0 = s1;
        curbuf ^= 1;
    }
}

// out[n][o] = sum_c KNclose[o][c] * x[n][c]
__global__ void __launch_bounds__(128) k_out(int xIdx, const float* __restrict__ KNc,
                                             float* __restrict__ out, int nN, int nOut) {
    __shared__ float Ks[40 * C];
    for (int i = threadIdx.x; i < nOut * C; i += 128) Ks[i] = KNc[i];
    __syncthreads();
    int n = blockIdx.x * 128 + threadIdx.x;
    if (n >= nN) return;
    const float* xr = g_buf[xIdx] + (long)n * C;
    float xv[C];
#pragma unroll
    for (int q = 0; q < C / 4; q++) {
        float4 v = ((const float4*)xr)[q];
        xv[4 * q] = v.x; xv[4 * q + 1] = v.y; xv[4 * q + 2] = v.z; xv[4 * q + 3] = v.w;
    }
    for (int o = 0; o < nOut; o++) {
        float acc = 0.0f;
#pragma unroll
        for (int c = 0; c < C; c++) acc = fmaf(Ks[o * C + c], xv[c], acc);
        out[(long)n * nOut + o] = acc;
    }
}

extern "C" void kernel_launch(void* const* d_in, const int* in_sizes, int n_in,
                              void* d_out, int out_size) {
    const float* xn = (const float*)d_in[0];
    const int* Iv = (const int*)d_in[1];
    const int* Jv = (const int*)d_in[2];
    int idx = 3;
    if (n_in >= 7 && in_sizes[3] == 1) idx = 4;   // skip scalar n_nodes input
    const float* K1  = (const float*)d_in[idx];
    const float* KN2 = (const float*)d_in[idx + 1];
    const float* KNc = (const float*)d_in[idx + 2];
    int nE = in_sizes[1];
    int nN = in_sizes[0] / CIN;
    int nLayer = in_sizes[idx + 1] / (C * C);
    int nOut = in_sizes[idx + 2] / C;
    float* out = (float*)d_out;

    cudaFuncSetAttribute(k_edge, cudaFuncAttributeMaxDynamicSharedMemorySize,
                         SMEM_EDGE);

    int nPB = (nN + 63) / 64;
    int nZB = (nN + 255) / 256;
    k_pz<<<nPB + nZB, 256>>>(xn, K1, nN, nPB);            // launch 0
    k_degree<<<(nE + 255) / 256, 256>>>(Jv, nE);          // launch 1
    k_Wd<<<(nE + 255) / 256, 256>>>(Iv, Jv, nE);          // launch 2

    int cur = 0, old = 1, nxt = 2;
    int n4 = nN * C / 4;
    for (int l = 0; l < nLayer; l++) {
        if (l > 0)
            k_init<<<(n4 + 255) / 256, 256>>>(cur, old, nxt, n4);
        k_edge<<<304, 256, SMEM_EDGE>>>(cur, nxt, Iv, Jv,
                                        KN2 + (long)l * C * C, nE);
        int t = old; old = cur; cur = nxt; nxt = t;
    }
    k_out<<<(nN + 127) / 128, 128>>>(cur, KNc, out, nN, nOut);
}